// round 14
// baseline (speedup 1.0000x reference)
#include <cuda_runtime.h>
#include <cstdint>
#include <math.h>

#define D_DIM    256
#define M_TOT    8192
#define N_TOT    8192
#define TM       64
#define TN       256
#define NTHREADS 256
#define TOTCH    ((N_TOT / TN) * 8)    // 256 chunks of 32 k
#define CAND_MAX 256
#define NBUF     4

#define SM_A_WORDS   4096              // s8 A frags: 16 KB
#define BUF_WORDS    2048              // one B chunk: 8 KB
#define SM_BYTES     (4 * (SM_A_WORDS + NBUF * BUF_WORDS))   // 49152

__device__ uint32_t g_bpk[N_TOT * D_DIM / 4];   // s8 B fragments (8KB chunks)
__device__ uint32_t g_xpk[M_TOT * D_DIM / 4];   // s8 A fragments (16KB CTA blocks)
__device__ float2   g_ecol[N_TOT];              // {esq, emax/127}
__device__ float    g_rsx[M_TOT];               // xmax_row/127
__device__ int      g_cand[M_TOT * CAND_MAX];
__device__ int      g_cnt[M_TOT];
__device__ unsigned g_mx2, g_me2, g_xmax, g_emax;   // atomicMax-idempotent

// ---------------------------------------------------------------------------
__device__ __forceinline__ uint32_t q4pack(float a, float b, float c, float d,
                                           float s) {
    int q0 = __float2int_rn(a * s), q1 = __float2int_rn(b * s);
    int q2 = __float2int_rn(c * s), q3 = __float2int_rn(d * s);
    return (uint32_t)(q0 & 0xFF) | ((uint32_t)(q1 & 0xFF) << 8)
         | ((uint32_t)(q2 & 0xFF) << 16) | ((uint32_t)(q3 & 0xFF) << 24);
}
__device__ __forceinline__ void mma_s8(int* d, uint4 a, uint2 b) {
    asm volatile(
        "mma.sync.aligned.m16n8k32.row.col.s32.s8.s8.s32 "
        "{%0,%1,%2,%3}, {%4,%5,%6,%7}, {%8,%9}, {%0,%1,%2,%3};"
        : "+r"(d[0]), "+r"(d[1]), "+r"(d[2]), "+r"(d[3])
        : "r"(a.x), "r"(a.y), "r"(a.z), "r"(a.w), "r"(b.x), "r"(b.y));
}
__device__ __forceinline__ uint32_t smem_u32(const void* p) {
    uint32_t a;
    asm("{ .reg .u64 t; cvta.to.shared.u64 t, %1; cvt.u32.u64 %0, t; }"
        : "=r"(a) : "l"(p));
    return a;
}
__device__ __forceinline__ void cp16(uint32_t dst, const void* src) {
    asm volatile("cp.async.cg.shared.global [%0], [%1], 16;"
                 :: "r"(dst), "l"(src) : "memory");
}
#define CP_COMMIT() asm volatile("cp.async.commit_group;" ::: "memory")
#define CP_WAIT(n)  asm volatile("cp.async.wait_group %0;" :: "n"(n) : "memory")

__device__ __forceinline__ unsigned enc(float f) {
    unsigned u = __float_as_uint(f);
    return (u & 0x80000000u) ? ~u : (u | 0x80000000u);
}
__device__ __forceinline__ float dec(unsigned u) {
    return (u & 0x80000000u) ? __uint_as_float(u & 0x7FFFFFFFu)
                             : __uint_as_float(~u);
}

// ---------------------------------------------------------------------------
// prep_embed: warp per code n -> esq/emax (g_ecol), s8 fragment-packed g_bpk.
// B frag (m16n8k32): col g, word w: k = kc*32 + w*16 + tig*4 + {0..3}
// chunk layout: [ntile*8+kc][nloc*8 + tig*2 + w]  (2048 words = 8 KB/chunk)
// ---------------------------------------------------------------------------
__global__ __launch_bounds__(256) void prep_embed(const float* __restrict__ embed) {
    __shared__ float bm2[8], bmx[8];
    const int wid  = threadIdx.x >> 5;
    const int lane = threadIdx.x & 31;
    const int n = blockIdx.x * 8 + wid;
    const int ntile = n >> 8, nloc = n & 255;

    const float* row = embed + (size_t)n * D_DIM;
    float s = 0.f, am = 1e-20f;
    const float4* r4 = (const float4*)row;
    #pragma unroll
    for (int i = lane; i < 64; i += 32) {
        float4 v = r4[i];
        s += v.x * v.x + v.y * v.y + v.z * v.z + v.w * v.w;
        am = fmaxf(am, fmaxf(fmaxf(fabsf(v.x), fabsf(v.y)),
                             fmaxf(fabsf(v.z), fabsf(v.w))));
    }
    #pragma unroll
    for (int o = 16; o; o >>= 1) {
        s  += __shfl_xor_sync(0xFFFFFFFFu, s, o);
        am  = fmaxf(am, __shfl_xor_sync(0xFFFFFFFFu, am, o));
    }
    if (lane == 0) {
        g_ecol[n] = make_float2(s, am / 127.0f);
        bm2[wid] = s; bmx[wid] = am;
    }

    const float qs = 127.0f / am;
    const int kc = lane >> 2, tig = lane & 3;
    #pragma unroll
    for (int w = 0; w < 2; w++) {
        int k0 = kc * 32 + w * 16 + tig * 4;
        uint32_t word = q4pack(row[k0], row[k0+1], row[k0+2], row[k0+3], qs);
        g_bpk[(size_t)(ntile * 8 + kc) * 2048 + nloc * 8 + tig * 2 + w] = word;
    }

    __syncthreads();
    if (threadIdx.x == 0) {
        float m2 = bm2[0], mx = bmx[0];
        #pragma unroll
        for (int i = 1; i < 8; i++) { m2 = fmaxf(m2, bm2[i]); mx = fmaxf(mx, bmx[i]); }
        atomicMax(&g_me2, __float_as_uint(m2));
        atomicMax(&g_emax, __float_as_uint(mx));
    }
}

// ---------------------------------------------------------------------------
// prep_x: warp per row r -> rsx, s8 A fragments in g_xpk, cnt reset, maxes.
// A frag (m16n8k32): lane (g,tig), regs {a0:row g,klo | a1:row g+8,klo |
//  a2:row g,khi | a3:row g+8,khi}; klo = tig*4, khi = 16+tig*4 (+kc*32).
// g_xpk word idx = (((r>>6)*4 + mt)*8 + kc)*128 + (g*4+tig)*4 + reg
// ---------------------------------------------------------------------------
__global__ __launch_bounds__(256) void prep_x(const float* __restrict__ x) {
    __shared__ float bm2[8], bmx[8];
    const int wid  = threadIdx.x >> 5;
    const int lane = threadIdx.x & 31;
    const int r = blockIdx.x * 8 + wid;

    const float* row = x + (size_t)r * D_DIM;
    float s = 0.f, am = 1e-20f;
    const float4* r4 = (const float4*)row;
    #pragma unroll
    for (int i = lane; i < 64; i += 32) {
        float4 v = r4[i];
        s += v.x * v.x + v.y * v.y + v.z * v.z + v.w * v.w;
        am = fmaxf(am, fmaxf(fmaxf(fabsf(v.x), fabsf(v.y)),
                             fmaxf(fabsf(v.z), fabsf(v.w))));
    }
    #pragma unroll
    for (int o = 16; o; o >>= 1) {
        s  += __shfl_xor_sync(0xFFFFFFFFu, s, o);
        am  = fmaxf(am, __shfl_xor_sync(0xFFFFFFFFu, am, o));
    }
    if (lane == 0) {
        g_rsx[r] = am / 127.0f;
        g_cnt[r] = 0;
        bm2[wid] = s; bmx[wid] = am;
    }

    const float qs = 127.0f / am;
    const int rloc = r & 63;
    const int mt = rloc >> 4, rl = rloc & 15;
    const int g = rl & 7, half = rl >> 3;
    const int kc = lane >> 2, tig = lane & 3;
    #pragma unroll
    for (int w = 0; w < 2; w++) {
        int k0 = kc * 32 + w * 16 + tig * 4;
        uint32_t word = q4pack(row[k0], row[k0+1], row[k0+2], row[k0+3], qs);
        int reg = w * 2 + half;
        g_xpk[(size_t)(((r >> 6) * 4 + mt) * 8 + kc) * 128 + (g * 4 + tig) * 4 + reg]
            = word;
    }

    __syncthreads();
    if (threadIdx.x == 0) {
        float m2 = bm2[0], mx = bmx[0];
        #pragma unroll
        for (int i = 1; i < 8; i++) { m2 = fmaxf(m2, bm2[i]); mx = fmaxf(mx, bmx[i]); }
        atomicMax(&g_mx2, __float_as_uint(m2));
        atomicMax(&g_xmax, __float_as_uint(mx));
    }
}

// ---------------------------------------------------------------------------
// Pass 1: s8 m16n8k32 screening GEMM, 256 thr / 8 warps (2m x 4n),
// warp tile 32x64. cp.async: A group first, then 4-buffered B chunks.
// ---------------------------------------------------------------------------
extern __shared__ uint32_t dsmw[];

__device__ __forceinline__ void append_cand(int grow, int col) {
    int idx = atomicAdd(&g_cnt[grow], 1);
    if (idx < CAND_MAX) g_cand[grow * CAND_MAX + idx] = col;
}

__global__ __launch_bounds__(NTHREADS, 1) void vq1_kernel() {
    __shared__ unsigned red[TM];
    const uint32_t smBase = smem_u32(dsmw);

    const int tid  = threadIdx.x;
    const int lane = tid & 31;
    const int wid  = tid >> 5;
    const int wm   = wid & 1;
    const int wn   = wid >> 1;
    const int g    = lane >> 2;
    const int tig  = lane & 3;
    const int mBase = blockIdx.x * TM;

    if (tid < TM) red[tid] = 0xFFFFFFFFu;

    // int8 screening threshold (rigorous): th = 2E + slack
    const float xm = __uint_as_float(g_xmax), em = __uint_as_float(g_emax);
    const float th = 2.0f * (0.5f * (xm / 127.0f) * 16.0f * sqrtf(__uint_as_float(g_me2))
                           + 0.5f * (em / 127.0f) * 16.0f * sqrtf(__uint_as_float(g_mx2))
                           + 64.0f * xm * em / 16129.0f) + 0.5f;

    // per-thread row scales (4 rows owned in epilogue)
    float rs[2][2];
    #pragma unroll
    for (int mt = 0; mt < 2; mt++) {
        rs[mt][0] = g_rsx[mBase + (wm * 2 + mt) * 16 + g];
        rs[mt][1] = g_rsx[mBase + (wm * 2 + mt) * 16 + g + 8];
    }

    // cp.async: A block first (group 0), then B chunks 0..2
    {
        const char* srcA = (const char*)g_xpk + (size_t)blockIdx.x * 16384;
        #pragma unroll
        for (int i = 0; i < 4; i++)
            cp16(smBase + i * 4096 + tid * 16, srcA + i * 4096 + tid * 16);
        CP_COMMIT();
    }
    #pragma unroll
    for (int c0 = 0; c0 < 3; c0++) {
        uint32_t dstB = smBase + SM_A_WORDS * 4 + (uint32_t)c0 * (BUF_WORDS * 4);
        const char* src = (const char*)g_bpk + (size_t)c0 * 8192;
        #pragma unroll
        for (int i = 0; i < 2; i++)
            cp16(dstB + i * 4096 + tid * 16, src + i * 4096 + tid * 16);
        CP_COMMIT();
    }

    int acc[2][8][4];
    const uint4* smA4 = (const uint4*)dsmw;

    for (int c = 0; c < TOTCH; c++) {
        if (c + 2 < TOTCH)      CP_WAIT(2);
        else if (c + 1 < TOTCH) CP_WAIT(1);
        else                    CP_WAIT(0);
        __syncthreads();

        const int kc  = c & 7;
        const int ntB = (c >> 3) * TN;

        if (kc == 0) {
            #pragma unroll
            for (int i = 0; i < 2; i++)
                #pragma unroll
                for (int j = 0; j < 8; j++)
                    #pragma unroll
                    for (int e = 0; e < 4; e++) acc[i][j][e] = 0;
        }

        const uint32_t* bb = dsmw + SM_A_WORDS + (c % NBUF) * BUF_WORDS;

        uint4 afr[2];
        #pragma unroll
        for (int mt = 0; mt < 2; mt++)
            afr[mt] = smA4[((wm * 2 + mt) * 8 + kc) * 32 + lane];
        #pragma unroll
        for (int ntl = 0; ntl < 8; ntl++) {
            uint2 bfr = *(const uint2*)&bb[(wn * 64 + ntl * 8 + g) * 8 + tig * 2];
            mma_s8(acc[0][ntl], afr[0], bfr);
            mma_s8(acc[1][ntl], afr[1], bfr);
        }

        if (c + 3 < TOTCH) {
            int nc = c + 3;
            uint32_t dstB = smBase + SM_A_WORDS * 4
                          + (uint32_t)(nc % NBUF) * (BUF_WORDS * 4);
            const char* src = (const char*)g_bpk + (size_t)nc * 8192;
            #pragma unroll
            for (int i = 0; i < 2; i++)
                cp16(dstB + i * 4096 + tid * 16, src + i * 4096 + tid * 16);
            CP_COMMIT();
        }

        if (kc == 7) {
            float rmin[4] = {3.4e38f, 3.4e38f, 3.4e38f, 3.4e38f};
            #pragma unroll
            for (int mt = 0; mt < 2; mt++)
                #pragma unroll
                for (int ntl = 0; ntl < 8; ntl++) {
                    int c0 = ntB + wn * 64 + ntl * 8 + 2 * tig;
                    float2 e0 = g_ecol[c0];
                    float2 e1 = g_ecol[c0 + 1];
                    float s0 = e0.x - 2.0f * (float)acc[mt][ntl][0] * (rs[mt][0] * e0.y);
                    float s1 = e1.x - 2.0f * (float)acc[mt][ntl][1] * (rs[mt][0] * e1.y);
                    float s2 = e0.x - 2.0f * (float)acc[mt][ntl][2] * (rs[mt][1] * e0.y);
                    float s3 = e1.x - 2.0f * (float)acc[mt][ntl][3] * (rs[mt][1] * e1.y);
                    rmin[mt*2]   = fminf(rmin[mt*2],   fminf(s0, s1));
                    rmin[mt*2+1] = fminf(rmin[mt*2+1], fminf(s2, s3));
                }
            #pragma unroll
            for (int q = 0; q < 4; q++) {
                int r = (wm * 2 + (q >> 1)) * 16 + g + (q & 1) * 8;
                atomicMin(&red[r], enc(rmin[q]));
            }
            __syncthreads();
            #pragma unroll
            for (int mt = 0; mt < 2; mt++) {
                int r0 = (wm * 2 + mt) * 16 + g;
                float t0 = dec(red[r0]) + th;
                float t1 = dec(red[r0 + 8]) + th;
                #pragma unroll
                for (int ntl = 0; ntl < 8; ntl++) {
                    int c0 = ntB + wn * 64 + ntl * 8 + 2 * tig;
                    float2 e0 = g_ecol[c0];
                    float2 e1 = g_ecol[c0 + 1];
                    float s0 = e0.x - 2.0f * (float)acc[mt][ntl][0] * (rs[mt][0] * e0.y);
                    float s1 = e1.x - 2.0f * (float)acc[mt][ntl][1] * (rs[mt][0] * e1.y);
                    float s2 = e0.x - 2.0f * (float)acc[mt][ntl][2] * (rs[mt][1] * e0.y);
                    float s3 = e1.x - 2.0f * (float)acc[mt][ntl][3] * (rs[mt][1] * e1.y);
                    if (s0 <= t0) append_cand(mBase + r0, c0);
                    if (s1 <= t0) append_cand(mBase + r0, c0 + 1);
                    if (s2 <= t1) append_cand(mBase + r0 + 8, c0);
                    if (s3 <= t1) append_cand(mBase + r0 + 8, c0 + 1);
                }
            }
        }
    }
}

// ---------------------------------------------------------------------------
// Pass 2: exact fp32 rescore (unchanged; candidate set is a superset by the
// int8 bound). Warp per row, whole warp per candidate, prefetched.
// ---------------------------------------------------------------------------
__global__ __launch_bounds__(256) void vq2_kernel(
    const float* __restrict__ x,
    const float* __restrict__ embed,
    float* __restrict__ out)
{
    const int wid  = threadIdx.x >> 5;
    const int lane = threadIdx.x & 31;
    const int R = blockIdx.x * 8 + wid;

    const float4* xr = (const float4*)(x + (size_t)R * D_DIM);
    float4 xa = xr[lane * 2], xb = xr[lane * 2 + 1];

    int cnt = g_cnt[R];
    float bd = 3.4e38f;
    int   bi = 0x7FFFFFFF;

    const bool uselist = (cnt <= CAND_MAX);
    const int  limit   = uselist ? cnt : N_TOT;
    const int* list    = g_cand + (size_t)R * CAND_MAX;

    int cd = uselist ? (limit > 0 ? list[0] : 0) : 0;
    const float4* er = (const float4*)(embed + (size_t)cd * D_DIM);
    float4 ea = er[lane * 2], eb = er[lane * 2 + 1];

    for (int ci = 0; ci < limit; ci++) {
        int curcd = cd;
        float4 ca = ea, cb = eb;
        if (ci + 1 < limit) {
            cd = uselist ? list[ci + 1] : (ci + 1);
            er = (const float4*)(embed + (size_t)cd * D_DIM);
            ea = er[lane * 2]; eb = er[lane * 2 + 1];
        }
        float d0 = xa.x * ca.x + xa.y * ca.y + xa.z * ca.z + xa.w * ca.w;
        float d1 = xb.x * cb.x + xb.y * cb.y + xb.z * cb.z + xb.w * cb.w;
        float dot = d0 + d1;
        #pragma unroll
        for (int o = 16; o; o >>= 1)
            dot += __shfl_xor_sync(0xFFFFFFFFu, dot, o);
        float s = g_ecol[curcd].x - 2.0f * dot;
        if (s < bd || (s == bd && curcd < bi)) { bd = s; bi = curcd; }
    }

    if (lane == 0) out[(size_t)M_TOT * D_DIM + R] = (float)bi;

    const float4* src = (const float4*)(embed + (size_t)bi * D_DIM);
    float4* dst = (float4*)(out + (size_t)R * D_DIM);
    #pragma unroll
    for (int t = lane; t < 64; t += 32) dst[t] = src[t];
}

// ---------------------------------------------------------------------------
extern "C" void kernel_launch(void* const* d_in, const int* in_sizes, int n_in,
                              void* d_out, int out_size)
{
    const float* x     = (const float*)d_in[0];
    const float* embed = (const float*)d_in[1];
    float*       out   = (float*)d_out;

    prep_embed<<<N_TOT / 8, 256>>>(embed);
    prep_x<<<M_TOT / 8, 256>>>(x);

    cudaFuncSetAttribute(vq1_kernel,
                         cudaFuncAttributeMaxDynamicSharedMemorySize, SM_BYTES);
    vq1_kernel<<<M_TOT / TM, NTHREADS, SM_BYTES>>>();

    vq2_kernel<<<M_TOT / 8, 256>>>(x, embed, out);
}

// round 15
// speedup vs baseline: 1.8510x; 1.8510x over previous
#include <cuda_runtime.h>
#include <cuda_bf16.h>
#include <cstdint>
#include <math.h>

#define D_DIM    256
#define M_TOT    8192
#define N_TOT    8192
#define TM       64
#define TN       256
#define NTHREADS 256
#define TOTCH    ((N_TOT / TN) * 8)    // 256 chunks of 32 k
#define CAND_MAX 256
#define NBUF     4

#define SM_A_WORDS   8192              // bf16 A frags: 32 KB
#define BUF_WORDS    4096              // one B chunk: 16 KB
#define SM_BYTES     (4 * (SM_A_WORDS + NBUF * BUF_WORDS))   // 98304

__device__ uint32_t g_bpk[N_TOT * D_DIM / 2];   // bf16 B fragments
__device__ float    g_esq[N_TOT];
__device__ int      g_cand[M_TOT * CAND_MAX];
__device__ int      g_cnt[M_TOT];
__device__ unsigned g_mx2, g_me2;   // atomicMax-idempotent across graph replays

// ---------------------------------------------------------------------------
__device__ __forceinline__ uint32_t bf16x2(float lo, float hi) {
    uint32_t r;
    asm("cvt.rn.bf16x2.f32 %0, %1, %2;" : "=r"(r) : "f"(hi), "f"(lo));
    return r;
}
__device__ __forceinline__ void mma_bf16(float* d, uint4 a, uint2 b) {
    asm volatile(
        "mma.sync.aligned.m16n8k16.row.col.f32.bf16.bf16.f32 "
        "{%0,%1,%2,%3}, {%4,%5,%6,%7}, {%8,%9}, {%0,%1,%2,%3};"
        : "+f"(d[0]), "+f"(d[1]), "+f"(d[2]), "+f"(d[3])
        : "r"(a.x), "r"(a.y), "r"(a.z), "r"(a.w), "r"(b.x), "r"(b.y));
}
__device__ __forceinline__ uint32_t smem_u32(const void* p) {
    uint32_t a;
    asm("{ .reg .u64 t; cvta.to.shared.u64 t, %1; cvt.u32.u64 %0, t; }"
        : "=r"(a) : "l"(p));
    return a;
}
__device__ __forceinline__ void cp16(uint32_t dst, const void* src) {
    asm volatile("cp.async.cg.shared.global [%0], [%1], 16;"
                 :: "r"(dst), "l"(src) : "memory");
}
#define CP_COMMIT() asm volatile("cp.async.commit_group;" ::: "memory")
#define CP_WAIT(n)  asm volatile("cp.async.wait_group %0;" :: "n"(n) : "memory")

__device__ __forceinline__ unsigned enc(float f) {
    unsigned u = __float_as_uint(f);
    return (u & 0x80000000u) ? ~u : (u | 0x80000000u);
}
__device__ __forceinline__ float dec(unsigned u) {
    return (u & 0x80000000u) ? __uint_as_float(u & 0x7FFFFFFFu)
                             : __uint_as_float(~u);
}

// ---------------------------------------------------------------------------
// prep_embed: warp per code row -> esq, bf16 fragment-packed g_bpk, norm max
// ---------------------------------------------------------------------------
__global__ __launch_bounds__(256) void prep_embed(const float* __restrict__ embed) {
    __shared__ float bmax[8];
    const int wid  = threadIdx.x >> 5;
    const int lane = threadIdx.x & 31;
    const int n = blockIdx.x * 8 + wid;
    const int ntile = n >> 8, nloc = n & 255;

    const float* row = embed + (size_t)n * D_DIM;
    float s = 0.f;
    const float4* r4 = (const float4*)row;
    #pragma unroll
    for (int i = lane; i < 64; i += 32) {
        float4 v = r4[i];
        s += v.x * v.x + v.y * v.y + v.z * v.z + v.w * v.w;
    }
    #pragma unroll
    for (int o = 16; o; o >>= 1) s += __shfl_xor_sync(0xFFFFFFFFu, s, o);
    if (lane == 0) { g_esq[n] = s; bmax[wid] = s; }

    #pragma unroll
    for (int t = 0; t < 4; t++) {
        int widx = t * 32 + lane;          // 0..127
        int kc  = widx >> 4;
        int r   = widx & 15;
        int k16 = r >> 3;
        int r2  = r & 7;
        int tig = r2 >> 1;
        int w   = r2 & 1;
        int kb  = kc * 32 + k16 * 16 + tig * 2 + w * 8;
        uint32_t val = bf16x2(__ldg(row + kb), __ldg(row + kb + 1));
        g_bpk[(size_t)(ntile * 8 + kc) * 4096 + k16 * 2048 + nloc * 8 + tig * 2 + w] = val;
    }

    __syncthreads();
    if (threadIdx.x == 0) {
        float m = bmax[0];
        #pragma unroll
        for (int i = 1; i < 8; i++) m = fmaxf(m, bmax[i]);
        atomicMax(&g_me2, __float_as_uint(m));
    }
}

__global__ __launch_bounds__(256) void prep_x(const float* __restrict__ x) {
    __shared__ float bmax[8];
    const int wid  = threadIdx.x >> 5;
    const int lane = threadIdx.x & 31;
    const int r = blockIdx.x * 8 + wid;

    const float4* r4 = (const float4*)(x + (size_t)r * D_DIM);
    float s = 0.f;
    #pragma unroll
    for (int i = lane; i < 64; i += 32) {
        float4 v = r4[i];
        s += v.x * v.x + v.y * v.y + v.z * v.z + v.w * v.w;
    }
    #pragma unroll
    for (int o = 16; o; o >>= 1) s += __shfl_xor_sync(0xFFFFFFFFu, s, o);
    if (lane == 0) { bmax[wid] = s; g_cnt[r] = 0; }

    __syncthreads();
    if (threadIdx.x == 0) {
        float m = bmax[0];
        #pragma unroll
        for (int i = 1; i < 8; i++) m = fmaxf(m, bmax[i]);
        atomicMax(&g_mx2, __float_as_uint(m));
    }
}

// ---------------------------------------------------------------------------
// Fused pass: bf16 m16n8k16 screening GEMM (R13 structure) + in-CTA exact
// fp32 rescore + gather tail. CTA owns 64 rows exclusively -> its candidate
// lists are complete after the main loop; __syncthreads gives visibility.
// ---------------------------------------------------------------------------
extern __shared__ uint32_t dsmw[];

__device__ __forceinline__ void append_cand(int grow, int col) {
    int idx = atomicAdd(&g_cnt[grow], 1);
    if (idx < CAND_MAX) g_cand[grow * CAND_MAX + idx] = col;
}

__global__ __launch_bounds__(NTHREADS, 1) void vq1_kernel(
    const float* __restrict__ x,
    const float* __restrict__ embed,
    float* __restrict__ out)
{
    __shared__ unsigned red[TM];
    uint32_t* smA = dsmw;
    const uint32_t smBase = smem_u32(dsmw);

    const int tid  = threadIdx.x;
    const int lane = tid & 31;
    const int wid  = tid >> 5;
    const int wm   = wid & 1;          // m half  (32 rows)
    const int wn   = wid >> 1;         // n quarter (64 cols)
    const int g    = lane >> 2;
    const int tig  = lane & 3;
    const int mBase = blockIdx.x * TM;

    if (tid < TM) red[tid] = 0xFFFFFFFFu;

    // bf16 screening bound
    const float th = 0.0316f * sqrtf(__uint_as_float(g_mx2) *
                                     __uint_as_float(g_me2)) + 0.25f;

    // prologue: issue B chunks 0..2
    #pragma unroll
    for (int c0 = 0; c0 < 3; c0++) {
        uint32_t dstB = smBase + SM_A_WORDS * 4 + (uint32_t)c0 * (BUF_WORDS * 4);
        const char* src = (const char*)g_bpk + (size_t)c0 * 16384;
        #pragma unroll
        for (int i = 0; i < 4; i++)
            cp16(dstB + i * 4096 + tid * 16, src + i * 4096 + tid * 16);
        CP_COMMIT();
    }

    // A: 64 rows x 256 k -> bf16 fragment-packed
    #pragma unroll 4
    for (int s = 0; s < 16; s++) {
        int fidx = s * NTHREADS + tid;
        int row = fidx >> 6, q = fidx & 63;
        float4 v = ((const float4*)(x + (size_t)(mBase + row) * D_DIM))[q];
        int mt = row >> 4, ml = row & 15;
        int gr = ml & 7, half = ml >> 3;
        int k0 = q * 4;
        int k16 = k0 >> 4, kl = k0 & 15;
        int hi8 = kl >> 3, tg0 = (kl & 7) >> 1;
        int reg = hi8 * 2 + half;
        int idx0 = ((mt * 16 + k16) * 32 + gr * 4 + tg0) * 4 + reg;
        smA[idx0]     = bf16x2(v.x, v.y);
        smA[idx0 + 4] = bf16x2(v.z, v.w);
    }

    float acc[2][8][4];

    for (int c = 0; c < TOTCH; c++) {
        if (c + 2 < TOTCH)      CP_WAIT(2);
        else if (c + 1 < TOTCH) CP_WAIT(1);
        else                    CP_WAIT(0);
        __syncthreads();

        const int kc  = c & 7;
        const int ntB = (c >> 3) * TN;

        if (kc == 0) {
            #pragma unroll
            for (int i = 0; i < 2; i++)
                #pragma unroll
                for (int j = 0; j < 8; j++)
                    #pragma unroll
                    for (int e = 0; e < 4; e++) acc[i][j][e] = 0.f;
        }

        const uint32_t* bb = dsmw + SM_A_WORDS + (c % NBUF) * BUF_WORDS;
        const uint4* smA4 = (const uint4*)smA;

        // 2 k16 steps, register double-buffered fragments
        uint4 afr[2][2];
        uint2 bfr[2][8];
        #pragma unroll
        for (int mt = 0; mt < 2; mt++)
            afr[0][mt] = smA4[((wm * 2 + mt) * 16 + kc * 2) * 32 + lane];
        #pragma unroll
        for (int ntl = 0; ntl < 8; ntl++)
            bfr[0][ntl] = *(const uint2*)&bb[(wn * 64 + ntl * 8 + g) * 8 + tig * 2];

        #pragma unroll
        for (int j = 0; j < 2; j++) {
            if (j == 0) {
                #pragma unroll
                for (int mt = 0; mt < 2; mt++)
                    afr[1][mt] = smA4[((wm * 2 + mt) * 16 + kc * 2 + 1) * 32 + lane];
                #pragma unroll
                for (int ntl = 0; ntl < 8; ntl++)
                    bfr[1][ntl] = *(const uint2*)&bb[2048 +
                        (wn * 64 + ntl * 8 + g) * 8 + tig * 2];
            }
            #pragma unroll
            for (int ntl = 0; ntl < 8; ntl++) {
                mma_bf16(acc[0][ntl], afr[j][0], bfr[j][ntl]);
                mma_bf16(acc[1][ntl], afr[j][1], bfr[j][ntl]);
            }
        }

        // refill freed buffer with chunk c+3
        if (c + 3 < TOTCH) {
            int nc = c + 3;
            uint32_t dstB = smBase + SM_A_WORDS * 4
                          + (uint32_t)(nc % NBUF) * (BUF_WORDS * 4);
            const char* src = (const char*)g_bpk + (size_t)nc * 16384;
            #pragma unroll
            for (int i = 0; i < 4; i++)
                cp16(dstB + i * 4096 + tid * 16, src + i * 4096 + tid * 16);
            CP_COMMIT();
        }

        if (kc == 7) {
            float rmin[4] = {3.4e38f, 3.4e38f, 3.4e38f, 3.4e38f};
            #pragma unroll
            for (int mt = 0; mt < 2; mt++)
                #pragma unroll
                for (int ntl = 0; ntl < 8; ntl++) {
                    int c0 = ntB + wn * 64 + ntl * 8 + 2 * tig;
                    float e0 = __ldg(&g_esq[c0]);
                    float e1 = __ldg(&g_esq[c0 + 1]);
                    float s0 = e0 - 2.0f * acc[mt][ntl][0];
                    float s1 = e1 - 2.0f * acc[mt][ntl][1];
                    float s2 = e0 - 2.0f * acc[mt][ntl][2];
                    float s3 = e1 - 2.0f * acc[mt][ntl][3];
                    rmin[mt*2]   = fminf(rmin[mt*2],   fminf(s0, s1));
                    rmin[mt*2+1] = fminf(rmin[mt*2+1], fminf(s2, s3));
                }
            #pragma unroll
            for (int q = 0; q < 4; q++) {
                int r = (wm * 2 + (q >> 1)) * 16 + g + (q & 1) * 8;
                atomicMin(&red[r], enc(rmin[q]));
            }
            __syncthreads();
            #pragma unroll
            for (int mt = 0; mt < 2; mt++) {
                int r0 = (wm * 2 + mt) * 16 + g;
                float t0 = dec(red[r0]) + th;
                float t1 = dec(red[r0 + 8]) + th;
                #pragma unroll
                for (int ntl = 0; ntl < 8; ntl++) {
                    int c0 = ntB + wn * 64 + ntl * 8 + 2 * tig;
                    float e0 = __ldg(&g_esq[c0]);
                    float e1 = __ldg(&g_esq[c0 + 1]);
                    float s0 = e0 - 2.0f * acc[mt][ntl][0];
                    float s1 = e1 - 2.0f * acc[mt][ntl][1];
                    float s2 = e0 - 2.0f * acc[mt][ntl][2];
                    float s3 = e1 - 2.0f * acc[mt][ntl][3];
                    if (s0 <= t0) append_cand(mBase + r0, c0);
                    if (s1 <= t0) append_cand(mBase + r0, c0 + 1);
                    if (s2 <= t1) append_cand(mBase + r0 + 8, c0);
                    if (s3 <= t1) append_cand(mBase + r0 + 8, c0 + 1);
                }
            }
        }
    }

    // =======================================================================
    // Fused tail: exact fp32 rescore + gather for this CTA's 64 rows.
    // __syncthreads gives CTA-wide visibility of g_cand/g_cnt writes above.
    // Warp w handles rows wid, wid+8, ..., wid+56 (whole warp per candidate).
    // =======================================================================
    __syncthreads();

    for (int rr = wid; rr < TM; rr += 8) {
        const int R = mBase + rr;
        const float4* xr = (const float4*)(x + (size_t)R * D_DIM);
        float4 xa = xr[lane * 2], xb = xr[lane * 2 + 1];

        int cnt = g_cnt[R];
        float bd = 3.4e38f;
        int   bi = 0x7FFFFFFF;

        const bool uselist = (cnt <= CAND_MAX);
        const int  limit   = uselist ? cnt : N_TOT;
        const int* list    = g_cand + (size_t)R * CAND_MAX;

        int cd = uselist ? (limit > 0 ? list[0] : 0) : 0;
        const float4* er = (const float4*)(embed + (size_t)cd * D_DIM);
        float4 ea = er[lane * 2], eb = er[lane * 2 + 1];

        for (int ci = 0; ci < limit; ci++) {
            int curcd = cd;
            float4 ca = ea, cb = eb;
            if (ci + 1 < limit) {                 // prefetch next row
                cd = uselist ? list[ci + 1] : (ci + 1);
                er = (const float4*)(embed + (size_t)cd * D_DIM);
                ea = er[lane * 2]; eb = er[lane * 2 + 1];
            }
            float d0 = xa.x * ca.x + xa.y * ca.y + xa.z * ca.z + xa.w * ca.w;
            float d1 = xb.x * cb.x + xb.y * cb.y + xb.z * cb.z + xb.w * cb.w;
            float dot = d0 + d1;
            #pragma unroll
            for (int o = 16; o; o >>= 1)
                dot += __shfl_xor_sync(0xFFFFFFFFu, dot, o);
            float s = __ldg(&g_esq[curcd]) - 2.0f * dot;
            if (s < bd || (s == bd && curcd < bi)) { bd = s; bi = curcd; }
        }

        if (lane == 0) out[(size_t)M_TOT * D_DIM + R] = (float)bi;

        const float4* src = (const float4*)(embed + (size_t)bi * D_DIM);
        float4* dst = (float4*)(out + (size_t)R * D_DIM);
        #pragma unroll
        for (int t = lane; t < 64; t += 32) dst[t] = src[t];
    }
}

// ---------------------------------------------------------------------------
extern "C" void kernel_launch(void* const* d_in, const int* in_sizes, int n_in,
                              void* d_out, int out_size)
{
    const float* x     = (const float*)d_in[0];
    const float* embed = (const float*)d_in[1];
    float*       out   = (float*)d_out;

    prep_embed<<<N_TOT / 8, 256>>>(embed);
    prep_x<<<M_TOT / 8, 256>>>(x);

    cudaFuncSetAttribute(vq1_kernel,
                         cudaFuncAttributeMaxDynamicSharedMemorySize, SM_BYTES);
    vq1_kernel<<<M_TOT / TM, NTHREADS, SM_BYTES>>>(x, embed, out);
}

// round 16
// speedup vs baseline: 2.5870x; 1.3977x over previous
#include <cuda_runtime.h>
#include <cuda_bf16.h>
#include <cstdint>
#include <math.h>

#define D_DIM    256
#define M_TOT    8192
#define N_TOT    8192
#define TM       32
#define TN       256
#define NTHREADS 256
#define TOTCH    ((N_TOT / TN) * 8)    // 256 chunks of 32 k
#define CAND_MAX 256
#define NBUF     4

#define SM_A_WORDS   4096              // bf16 A frags (32 rows): 16 KB
#define BUF_WORDS    4096              // one B chunk: 16 KB
#define SM_BYTES     (4 * (SM_A_WORDS + NBUF * BUF_WORDS))   // 81920

__device__ uint32_t g_bpk[N_TOT * D_DIM / 2];   // bf16 B fragments
__device__ float    g_esq[N_TOT];
__device__ int      g_cand[M_TOT * CAND_MAX];
__device__ int      g_cnt[M_TOT];
__device__ unsigned g_mx2, g_me2;   // atomicMax-idempotent across graph replays

// ---------------------------------------------------------------------------
__device__ __forceinline__ uint32_t bf16x2(float lo, float hi) {
    uint32_t r;
    asm("cvt.rn.bf16x2.f32 %0, %1, %2;" : "=r"(r) : "f"(hi), "f"(lo));
    return r;
}
__device__ __forceinline__ void mma_bf16(float* d, uint4 a, uint2 b) {
    asm volatile(
        "mma.sync.aligned.m16n8k16.row.col.f32.bf16.bf16.f32 "
        "{%0,%1,%2,%3}, {%4,%5,%6,%7}, {%8,%9}, {%0,%1,%2,%3};"
        : "+f"(d[0]), "+f"(d[1]), "+f"(d[2]), "+f"(d[3])
        : "r"(a.x), "r"(a.y), "r"(a.z), "r"(a.w), "r"(b.x), "r"(b.y));
}
__device__ __forceinline__ uint32_t smem_u32(const void* p) {
    uint32_t a;
    asm("{ .reg .u64 t; cvta.to.shared.u64 t, %1; cvt.u32.u64 %0, t; }"
        : "=r"(a) : "l"(p));
    return a;
}
__device__ __forceinline__ void cp16(uint32_t dst, const void* src) {
    asm volatile("cp.async.cg.shared.global [%0], [%1], 16;"
                 :: "r"(dst), "l"(src) : "memory");
}
#define CP_COMMIT() asm volatile("cp.async.commit_group;" ::: "memory")
#define CP_WAIT(n)  asm volatile("cp.async.wait_group %0;" :: "n"(n) : "memory")

__device__ __forceinline__ unsigned enc(float f) {
    unsigned u = __float_as_uint(f);
    return (u & 0x80000000u) ? ~u : (u | 0x80000000u);
}
__device__ __forceinline__ float dec(unsigned u) {
    return (u & 0x80000000u) ? __uint_as_float(u & 0x7FFFFFFFu)
                             : __uint_as_float(~u);
}

// ---------------------------------------------------------------------------
// prep_embed: warp per code row -> esq, bf16 fragment-packed g_bpk, norm max
// ---------------------------------------------------------------------------
__global__ __launch_bounds__(256) void prep_embed(const float* __restrict__ embed) {
    __shared__ float bmax[8];
    const int wid  = threadIdx.x >> 5;
    const int lane = threadIdx.x & 31;
    const int n = blockIdx.x * 8 + wid;
    const int ntile = n >> 8, nloc = n & 255;

    const float* row = embed + (size_t)n * D_DIM;
    float s = 0.f;
    const float4* r4 = (const float4*)row;
    #pragma unroll
    for (int i = lane; i < 64; i += 32) {
        float4 v = r4[i];
        s += v.x * v.x + v.y * v.y + v.z * v.z + v.w * v.w;
    }
    #pragma unroll
    for (int o = 16; o; o >>= 1) s += __shfl_xor_sync(0xFFFFFFFFu, s, o);
    if (lane == 0) { g_esq[n] = s; bmax[wid] = s; }

    #pragma unroll
    for (int t = 0; t < 4; t++) {
        int widx = t * 32 + lane;          // 0..127
        int kc  = widx >> 4;
        int r   = widx & 15;
        int k16 = r >> 3;
        int r2  = r & 7;
        int tig = r2 >> 1;
        int w   = r2 & 1;
        int kb  = kc * 32 + k16 * 16 + tig * 2 + w * 8;
        uint32_t val = bf16x2(__ldg(row + kb), __ldg(row + kb + 1));
        g_bpk[(size_t)(ntile * 8 + kc) * 4096 + k16 * 2048 + nloc * 8 + tig * 2 + w] = val;
    }

    __syncthreads();
    if (threadIdx.x == 0) {
        float m = bmax[0];
        #pragma unroll
        for (int i = 1; i < 8; i++) m = fmaxf(m, bmax[i]);
        atomicMax(&g_me2, __float_as_uint(m));
    }
}

__global__ __launch_bounds__(256) void prep_x(const float* __restrict__ x) {
    __shared__ float bmax[8];
    const int wid  = threadIdx.x >> 5;
    const int lane = threadIdx.x & 31;
    const int r = blockIdx.x * 8 + wid;

    const float4* r4 = (const float4*)(x + (size_t)r * D_DIM);
    float s = 0.f;
    #pragma unroll
    for (int i = lane; i < 64; i += 32) {
        float4 v = r4[i];
        s += v.x * v.x + v.y * v.y + v.z * v.z + v.w * v.w;
    }
    #pragma unroll
    for (int o = 16; o; o >>= 1) s += __shfl_xor_sync(0xFFFFFFFFu, s, o);
    if (lane == 0) { bmax[wid] = s; g_cnt[r] = 0; }

    __syncthreads();
    if (threadIdx.x == 0) {
        float m = bmax[0];
        #pragma unroll
        for (int i = 1; i < 8; i++) m = fmaxf(m, bmax[i]);
        atomicMax(&g_mx2, __float_as_uint(m));
    }
}

// ---------------------------------------------------------------------------
// Pass 1: bf16 m16n8k16 screening GEMM. TM=32 rows per CTA, grid 256,
// 2 CTAs/SM (occupancy 2). 8 warps, warp tile 32x32 (2mt x 4ntl), wn = wid.
// cp.async 4-buffer B; register double-buffered fragments.
// ---------------------------------------------------------------------------
extern __shared__ uint32_t dsmw[];

__device__ __forceinline__ void append_cand(int grow, int col) {
    int idx = atomicAdd(&g_cnt[grow], 1);
    if (idx < CAND_MAX) g_cand[grow * CAND_MAX + idx] = col;
}

__global__ __launch_bounds__(NTHREADS, 2) void vq1_kernel(
    const float* __restrict__ x)
{
    __shared__ unsigned red[TM];
    uint32_t* smA = dsmw;
    const uint32_t smBase = smem_u32(dsmw);

    const int tid  = threadIdx.x;
    const int lane = tid & 31;
    const int wid  = tid >> 5;
    const int wn   = wid;              // n eighth (32 cols)
    const int g    = lane >> 2;
    const int tig  = lane & 3;
    const int mBase = blockIdx.x * TM;

    if (tid < TM) red[tid] = 0xFFFFFFFFu;

    // bf16 screening bound
    const float th = 0.0316f * sqrtf(__uint_as_float(g_mx2) *
                                     __uint_as_float(g_me2)) + 0.25f;

    // prologue: issue B chunks 0..2
    #pragma unroll
    for (int c0 = 0; c0 < 3; c0++) {
        uint32_t dstB = smBase + SM_A_WORDS * 4 + (uint32_t)c0 * (BUF_WORDS * 4);
        const char* src = (const char*)g_bpk + (size_t)c0 * 16384;
        #pragma unroll
        for (int i = 0; i < 4; i++)
            cp16(dstB + i * 4096 + tid * 16, src + i * 4096 + tid * 16);
        CP_COMMIT();
    }

    // A: 32 rows x 256 k -> bf16 fragment-packed
    #pragma unroll 4
    for (int s = 0; s < 8; s++) {
        int fidx = s * NTHREADS + tid;
        int row = fidx >> 6, q = fidx & 63;
        float4 v = ((const float4*)(x + (size_t)(mBase + row) * D_DIM))[q];
        int mt = row >> 4, ml = row & 15;
        int gr = ml & 7, half = ml >> 3;
        int k0 = q * 4;
        int k16 = k0 >> 4, kl = k0 & 15;
        int hi8 = kl >> 3, tg0 = (kl & 7) >> 1;
        int reg = hi8 * 2 + half;
        int idx0 = ((mt * 16 + k16) * 32 + gr * 4 + tg0) * 4 + reg;
        smA[idx0]     = bf16x2(v.x, v.y);
        smA[idx0 + 4] = bf16x2(v.z, v.w);
    }

    float acc[2][4][4];

    for (int c = 0; c < TOTCH; c++) {
        if (c + 2 < TOTCH)      CP_WAIT(2);
        else if (c + 1 < TOTCH) CP_WAIT(1);
        else                    CP_WAIT(0);
        __syncthreads();

        const int kc  = c & 7;
        const int ntB = (c >> 3) * TN;

        if (kc == 0) {
            #pragma unroll
            for (int i = 0; i < 2; i++)
                #pragma unroll
                for (int j = 0; j < 4; j++)
                    #pragma unroll
                    for (int e = 0; e < 4; e++) acc[i][j][e] = 0.f;
        }

        const uint32_t* bb = dsmw + SM_A_WORDS + (c % NBUF) * BUF_WORDS;
        const uint4* smA4 = (const uint4*)smA;

        // 2 k16 steps, register double-buffered fragments
        uint4 afr[2][2];
        uint2 bfr[2][4];
        #pragma unroll
        for (int mt = 0; mt < 2; mt++)
            afr[0][mt] = smA4[(mt * 16 + kc * 2) * 32 + lane];
        #pragma unroll
        for (int ntl = 0; ntl < 4; ntl++)
            bfr[0][ntl] = *(const uint2*)&bb[(wn * 32 + ntl * 8 + g) * 8 + tig * 2];

        #pragma unroll
        for (int j = 0; j < 2; j++) {
            if (j == 0) {
                #pragma unroll
                for (int mt = 0; mt < 2; mt++)
                    afr[1][mt] = smA4[(mt * 16 + kc * 2 + 1) * 32 + lane];
                #pragma unroll
                for (int ntl = 0; ntl < 4; ntl++)
                    bfr[1][ntl] = *(const uint2*)&bb[2048 +
                        (wn * 32 + ntl * 8 + g) * 8 + tig * 2];
            }
            #pragma unroll
            for (int ntl = 0; ntl < 4; ntl++) {
                mma_bf16(acc[0][ntl], afr[j][0], bfr[j][ntl]);
                mma_bf16(acc[1][ntl], afr[j][1], bfr[j][ntl]);
            }
        }

        // refill freed buffer with chunk c+3
        if (c + 3 < TOTCH) {
            int nc = c + 3;
            uint32_t dstB = smBase + SM_A_WORDS * 4
                          + (uint32_t)(nc % NBUF) * (BUF_WORDS * 4);
            const char* src = (const char*)g_bpk + (size_t)nc * 16384;
            #pragma unroll
            for (int i = 0; i < 4; i++)
                cp16(dstB + i * 4096 + tid * 16, src + i * 4096 + tid * 16);
            CP_COMMIT();
        }

        if (kc == 7) {
            float rmin[4] = {3.4e38f, 3.4e38f, 3.4e38f, 3.4e38f};
            #pragma unroll
            for (int mt = 0; mt < 2; mt++)
                #pragma unroll
                for (int ntl = 0; ntl < 4; ntl++) {
                    int c0 = ntB + wn * 32 + ntl * 8 + 2 * tig;
                    float e0 = __ldg(&g_esq[c0]);
                    float e1 = __ldg(&g_esq[c0 + 1]);
                    float s0 = e0 - 2.0f * acc[mt][ntl][0];
                    float s1 = e1 - 2.0f * acc[mt][ntl][1];
                    float s2 = e0 - 2.0f * acc[mt][ntl][2];
                    float s3 = e1 - 2.0f * acc[mt][ntl][3];
                    rmin[mt*2]   = fminf(rmin[mt*2],   fminf(s0, s1));
                    rmin[mt*2+1] = fminf(rmin[mt*2+1], fminf(s2, s3));
                }
            #pragma unroll
            for (int q = 0; q < 4; q++) {
                int r = (q >> 1) * 16 + g + (q & 1) * 8;
                atomicMin(&red[r], enc(rmin[q]));
            }
            __syncthreads();
            #pragma unroll
            for (int mt = 0; mt < 2; mt++) {
                int r0 = mt * 16 + g;
                float t0 = dec(red[r0]) + th;
                float t1 = dec(red[r0 + 8]) + th;
                #pragma unroll
                for (int ntl = 0; ntl < 4; ntl++) {
                    int c0 = ntB + wn * 32 + ntl * 8 + 2 * tig;
                    float e0 = __ldg(&g_esq[c0]);
                    float e1 = __ldg(&g_esq[c0 + 1]);
                    float s0 = e0 - 2.0f * acc[mt][ntl][0];
                    float s1 = e1 - 2.0f * acc[mt][ntl][1];
                    float s2 = e0 - 2.0f * acc[mt][ntl][2];
                    float s3 = e1 - 2.0f * acc[mt][ntl][3];
                    if (s0 <= t0) append_cand(mBase + r0, c0);
                    if (s1 <= t0) append_cand(mBase + r0, c0 + 1);
                    if (s2 <= t1) append_cand(mBase + r0 + 8, c0);
                    if (s3 <= t1) append_cand(mBase + r0 + 8, c0 + 1);
                }
            }
        }
    }
}

// ---------------------------------------------------------------------------
// Pass 2: fp32 rescore, warp per row, whole warp per candidate, prefetched.
// ---------------------------------------------------------------------------
__global__ __launch_bounds__(256) void vq2_kernel(
    const float* __restrict__ x,
    const float* __restrict__ embed,
    float* __restrict__ out)
{
    const int wid  = threadIdx.x >> 5;
    const int lane = threadIdx.x & 31;
    const int R = blockIdx.x * 8 + wid;

    const float4* xr = (const float4*)(x + (size_t)R * D_DIM);
    float4 xa = xr[lane * 2], xb = xr[lane * 2 + 1];

    int cnt = g_cnt[R];
    float bd = 3.4e38f;
    int   bi = 0x7FFFFFFF;

    const bool uselist = (cnt <= CAND_MAX);
    const int  limit   = uselist ? cnt : N_TOT;
    const int* list    = g_cand + (size_t)R * CAND_MAX;

    int cd = uselist ? (limit > 0 ? list[0] : 0) : 0;
    const float4* er = (const float4*)(embed + (size_t)cd * D_DIM);
    float4 ea = er[lane * 2], eb = er[lane * 2 + 1];

    for (int ci = 0; ci < limit; ci++) {
        int curcd = cd;
        float4 ca = ea, cb = eb;
        if (ci + 1 < limit) {
            cd = uselist ? list[ci + 1] : (ci + 1);
            er = (const float4*)(embed + (size_t)cd * D_DIM);
            ea = er[lane * 2]; eb = er[lane * 2 + 1];
        }
        float d0 = xa.x * ca.x + xa.y * ca.y + xa.z * ca.z + xa.w * ca.w;
        float d1 = xb.x * cb.x + xb.y * cb.y + xb.z * cb.z + xb.w * cb.w;
        float dot = d0 + d1;
        #pragma unroll
        for (int o = 16; o; o >>= 1)
            dot += __shfl_xor_sync(0xFFFFFFFFu, dot, o);
        float s = g_esq[curcd] - 2.0f * dot;
        if (s < bd || (s == bd && curcd < bi)) { bd = s; bi = curcd; }
    }

    if (lane == 0) out[(size_t)M_TOT * D_DIM + R] = (float)bi;

    const float4* src = (const float4*)(embed + (size_t)bi * D_DIM);
    float4* dst = (float4*)(out + (size_t)R * D_DIM);
    #pragma unroll
    for (int t = lane; t < 64; t += 32) dst[t] = src[t];
}

// ---------------------------------------------------------------------------
extern "C" void kernel_launch(void* const* d_in, const int* in_sizes, int n_in,
                              void* d_out, int out_size)
{
    const float* x     = (const float*)d_in[0];
    const float* embed = (const float*)d_in[1];
    float*       out   = (float*)d_out;

    prep_embed<<<N_TOT / 8, 256>>>(embed);
    prep_x<<<M_TOT / 8, 256>>>(x);

    cudaFuncSetAttribute(vq1_kernel,
                         cudaFuncAttributeMaxDynamicSharedMemorySize, SM_BYTES);
    vq1_kernel<<<M_TOT / TM, NTHREADS, SM_BYTES>>>(x);

    vq2_kernel<<<M_TOT / 8, 256>>>(x, embed, out);
}

// round 17
// speedup vs baseline: 2.6240x; 1.0143x over previous
#include <cuda_runtime.h>
#include <cuda_bf16.h>
#include <cstdint>
#include <math.h>

#define D_DIM    256
#define M_TOT    8192
#define N_TOT    8192
#define TM       32
#define TN       256
#define NTHREADS 256
#define TOTCH    ((N_TOT / TN) * 8)    // 256 chunks of 32 k
#define CAND_MAX 256
#define NBUF     4

#define SM_A_WORDS   4096              // bf16 A frags (32 rows): 16 KB
#define BUF_WORDS    4096              // one B chunk: 16 KB
#define SM_MBAR_OFF  (4 * (SM_A_WORDS + NBUF * BUF_WORDS))   // 81920
#define SM_BYTES     (SM_MBAR_OFF + 64)

__device__ uint32_t g_bpk[N_TOT * D_DIM / 2];   // bf16 B fragments
__device__ float    g_esq[N_TOT];
__device__ int      g_cand[M_TOT * CAND_MAX];
__device__ int      g_cnt[M_TOT];
__device__ unsigned g_mx2, g_me2;   // atomicMax-idempotent across graph replays

// ---------------------------------------------------------------------------
__device__ __forceinline__ uint32_t bf16x2(float lo, float hi) {
    uint32_t r;
    asm("cvt.rn.bf16x2.f32 %0, %1, %2;" : "=r"(r) : "f"(hi), "f"(lo));
    return r;
}
__device__ __forceinline__ void mma_bf16(float* d, uint4 a, uint2 b) {
    asm volatile(
        "mma.sync.aligned.m16n8k16.row.col.f32.bf16.bf16.f32 "
        "{%0,%1,%2,%3}, {%4,%5,%6,%7}, {%8,%9}, {%0,%1,%2,%3};"
        : "+f"(d[0]), "+f"(d[1]), "+f"(d[2]), "+f"(d[3])
        : "r"(a.x), "r"(a.y), "r"(a.z), "r"(a.w), "r"(b.x), "r"(b.y));
}
__device__ __forceinline__ uint32_t smem_u32(const void* p) {
    uint32_t a;
    asm("{ .reg .u64 t; cvta.to.shared.u64 t, %1; cvt.u32.u64 %0, t; }"
        : "=r"(a) : "l"(p));
    return a;
}
// one-instruction bulk copy gmem -> smem with mbarrier completion
__device__ __forceinline__ void bulk_cp(uint32_t dst, const void* src,
                                        uint32_t bytes, uint32_t mbar) {
    asm volatile(
        "cp.async.bulk.shared::cta.global.mbarrier::complete_tx::bytes "
        "[%0], [%1], %2, [%3];"
        :: "r"(dst), "l"(src), "r"(bytes), "r"(mbar) : "memory");
}
#define MBAR_INIT(a, n) \
    asm volatile("mbarrier.init.shared.b64 [%0], %1;" :: "r"(a), "r"(n) : "memory")
#define MBAR_EXPECT_TX(a, n) \
    asm volatile("mbarrier.arrive.expect_tx.shared.b64 _, [%0], %1;" \
                 :: "r"(a), "r"((uint32_t)(n)) : "memory")
__device__ __forceinline__ void mbar_wait(uint32_t mbar, uint32_t parity) {
    asm volatile(
        "{ .reg .pred P1;\n\t"
        "WL_%=:\n\t"
        "mbarrier.try_wait.parity.acquire.cta.shared::cta.b64 P1, [%0], %1, 0x989680;\n\t"
        "@P1 bra.uni WD_%=;\n\t"
        "bra.uni WL_%=;\n\t"
        "WD_%=: }"
        :: "r"(mbar), "r"(parity) : "memory");
}

__device__ __forceinline__ unsigned enc(float f) {
    unsigned u = __float_as_uint(f);
    return (u & 0x80000000u) ? ~u : (u | 0x80000000u);
}
__device__ __forceinline__ float dec(unsigned u) {
    return (u & 0x80000000u) ? __uint_as_float(u & 0x7FFFFFFFu)
                             : __uint_as_float(~u);
}

// ---------------------------------------------------------------------------
// prep_embed: warp per code row -> esq, bf16 fragment-packed g_bpk, norm max
// ---------------------------------------------------------------------------
__global__ __launch_bounds__(256) void prep_embed(const float* __restrict__ embed) {
    __shared__ float bmax[8];
    const int wid  = threadIdx.x >> 5;
    const int lane = threadIdx.x & 31;
    const int n = blockIdx.x * 8 + wid;
    const int ntile = n >> 8, nloc = n & 255;

    const float* row = embed + (size_t)n * D_DIM;
    float s = 0.f;
    const float4* r4 = (const float4*)row;
    #pragma unroll
    for (int i = lane; i < 64; i += 32) {
        float4 v = r4[i];
        s += v.x * v.x + v.y * v.y + v.z * v.z + v.w * v.w;
    }
    #pragma unroll
    for (int o = 16; o; o >>= 1) s += __shfl_xor_sync(0xFFFFFFFFu, s, o);
    if (lane == 0) { g_esq[n] = s; bmax[wid] = s; }

    #pragma unroll
    for (int t = 0; t < 4; t++) {
        int widx = t * 32 + lane;          // 0..127
        int kc  = widx >> 4;
        int r   = widx & 15;
        int k16 = r >> 3;
        int r2  = r & 7;
        int tig = r2 >> 1;
        int w   = r2 & 1;
        int kb  = kc * 32 + k16 * 16 + tig * 2 + w * 8;
        uint32_t val = bf16x2(__ldg(row + kb), __ldg(row + kb + 1));
        g_bpk[(size_t)(ntile * 8 + kc) * 4096 + k16 * 2048 + nloc * 8 + tig * 2 + w] = val;
    }

    __syncthreads();
    if (threadIdx.x == 0) {
        float m = bmax[0];
        #pragma unroll
        for (int i = 1; i < 8; i++) m = fmaxf(m, bmax[i]);
        atomicMax(&g_me2, __float_as_uint(m));
    }
}

__global__ __launch_bounds__(256) void prep_x(const float* __restrict__ x) {
    __shared__ float bmax[8];
    const int wid  = threadIdx.x >> 5;
    const int lane = threadIdx.x & 31;
    const int r = blockIdx.x * 8 + wid;

    const float4* r4 = (const float4*)(x + (size_t)r * D_DIM);
    float s = 0.f;
    #pragma unroll
    for (int i = lane; i < 64; i += 32) {
        float4 v = r4[i];
        s += v.x * v.x + v.y * v.y + v.z * v.z + v.w * v.w;
    }
    #pragma unroll
    for (int o = 16; o; o >>= 1) s += __shfl_xor_sync(0xFFFFFFFFu, s, o);
    if (lane == 0) { bmax[wid] = s; g_cnt[r] = 0; }

    __syncthreads();
    if (threadIdx.x == 0) {
        float m = bmax[0];
        #pragma unroll
        for (int i = 1; i < 8; i++) m = fmaxf(m, bmax[i]);
        atomicMax(&g_mx2, __float_as_uint(m));
    }
}

// ---------------------------------------------------------------------------
// Pass 1: bf16 m16n8k16 screening GEMM. TM=32, grid 256, 2 CTAs/SM.
// B chunks via single-instruction cp.async.bulk + mbarrier (4 buffers).
// ---------------------------------------------------------------------------
extern __shared__ uint32_t dsmw[];

__device__ __forceinline__ void append_cand(int grow, int col) {
    int idx = atomicAdd(&g_cnt[grow], 1);
    if (idx < CAND_MAX) g_cand[grow * CAND_MAX + idx] = col;
}

__global__ __launch_bounds__(NTHREADS, 2) void vq1_kernel(
    const float* __restrict__ x)
{
    __shared__ unsigned red[TM];
    uint32_t* smA = dsmw;
    const uint32_t smBase = smem_u32(dsmw);
    const uint32_t mbarBase = smBase + SM_MBAR_OFF;

    const int tid  = threadIdx.x;
    const int lane = tid & 31;
    const int wid  = tid >> 5;
    const int wn   = wid;              // n eighth (32 cols)
    const int g    = lane >> 2;
    const int tig  = lane & 3;
    const int mBase = blockIdx.x * TM;

    if (tid < TM) red[tid] = 0xFFFFFFFFu;

    // bf16 screening bound
    const float th = 0.0316f * sqrtf(__uint_as_float(g_mx2) *
                                     __uint_as_float(g_me2)) + 0.25f;

    // init mbarriers, then prologue fills of B chunks 0..2
    if (tid == 0) {
        #pragma unroll
        for (int b = 0; b < NBUF; b++) MBAR_INIT(mbarBase + b * 8, 1);
    }
    __syncthreads();
    if (tid == 0) {
        #pragma unroll
        for (int c0 = 0; c0 < 3; c0++) {
            MBAR_EXPECT_TX(mbarBase + c0 * 8, BUF_WORDS * 4);
            bulk_cp(smBase + (SM_A_WORDS + c0 * BUF_WORDS) * 4,
                    (const char*)g_bpk + (size_t)c0 * 16384,
                    BUF_WORDS * 4, mbarBase + c0 * 8);
        }
    }

    // A: 32 rows x 256 k -> bf16 fragment-packed
    #pragma unroll 4
    for (int s = 0; s < 8; s++) {
        int fidx = s * NTHREADS + tid;
        int row = fidx >> 6, q = fidx & 63;
        float4 v = ((const float4*)(x + (size_t)(mBase + row) * D_DIM))[q];
        int mt = row >> 4, ml = row & 15;
        int gr = ml & 7, half = ml >> 3;
        int k0 = q * 4;
        int k16 = k0 >> 4, kl = k0 & 15;
        int hi8 = kl >> 3, tg0 = (kl & 7) >> 1;
        int reg = hi8 * 2 + half;
        int idx0 = ((mt * 16 + k16) * 32 + gr * 4 + tg0) * 4 + reg;
        smA[idx0]     = bf16x2(v.x, v.y);
        smA[idx0 + 4] = bf16x2(v.z, v.w);
    }

    float acc[2][4][4];

    for (int c = 0; c < TOTCH; c++) {
        // all warps finished compute of chunk c-1 -> buffer (c+3)%4 is free
        __syncthreads();
        if (tid == 0 && c + 3 < TOTCH) {
            int nc = c + 3, b = nc & 3;
            MBAR_EXPECT_TX(mbarBase + b * 8, BUF_WORDS * 4);
            bulk_cp(smBase + (SM_A_WORDS + b * BUF_WORDS) * 4,
                    (const char*)g_bpk + (size_t)nc * 16384,
                    BUF_WORDS * 4, mbarBase + b * 8);
        }
        // wait for chunk c's buffer
        mbar_wait(mbarBase + (c & 3) * 8, (c >> 2) & 1);

        const int kc  = c & 7;
        const int ntB = (c >> 3) * TN;

        if (kc == 0) {
            #pragma unroll
            for (int i = 0; i < 2; i++)
                #pragma unroll
                for (int j = 0; j < 4; j++)
                    #pragma unroll
                    for (int e = 0; e < 4; e++) acc[i][j][e] = 0.f;
        }

        const uint32_t* bb = dsmw + SM_A_WORDS + (c & 3) * BUF_WORDS;
        const uint4* smA4 = (const uint4*)smA;

        // 2 k16 steps, register double-buffered fragments
        uint4 afr[2][2];
        uint2 bfr[2][4];
        #pragma unroll
        for (int mt = 0; mt < 2; mt++)
            afr[0][mt] = smA4[(mt * 16 + kc * 2) * 32 + lane];
        #pragma unroll
        for (int ntl = 0; ntl < 4; ntl++)
            bfr[0][ntl] = *(const uint2*)&bb[(wn * 32 + ntl * 8 + g) * 8 + tig * 2];

        #pragma unroll
        for (int j = 0; j < 2; j++) {
            if (j == 0) {
                #pragma unroll
                for (int mt = 0; mt < 2; mt++)
                    afr[1][mt] = smA4[(mt * 16 + kc * 2 + 1) * 32 + lane];
                #pragma unroll
                for (int ntl = 0; ntl < 4; ntl++)
                    bfr[1][ntl] = *(const uint2*)&bb[2048 +
                        (wn * 32 + ntl * 8 + g) * 8 + tig * 2];
            }
            #pragma unroll
            for (int ntl = 0; ntl < 4; ntl++) {
                mma_bf16(acc[0][ntl], afr[j][0], bfr[j][ntl]);
                mma_bf16(acc[1][ntl], afr[j][1], bfr[j][ntl]);
            }
        }

        if (kc == 7) {
            float rmin[4] = {3.4e38f, 3.4e38f, 3.4e38f, 3.4e38f};
            #pragma unroll
            for (int mt = 0; mt < 2; mt++)
                #pragma unroll
                for (int ntl = 0; ntl < 4; ntl++) {
                    int c0 = ntB + wn * 32 + ntl * 8 + 2 * tig;
                    float e0 = __ldg(&g_esq[c0]);
                    float e1 = __ldg(&g_esq[c0 + 1]);
                    float s0 = e0 - 2.0f * acc[mt][ntl][0];
                    float s1 = e1 - 2.0f * acc[mt][ntl][1];
                    float s2 = e0 - 2.0f * acc[mt][ntl][2];
                    float s3 = e1 - 2.0f * acc[mt][ntl][3];
                    rmin[mt*2]   = fminf(rmin[mt*2],   fminf(s0, s1));
                    rmin[mt*2+1] = fminf(rmin[mt*2+1], fminf(s2, s3));
                }
            #pragma unroll
            for (int q = 0; q < 4; q++) {
                int r = (q >> 1) * 16 + g + (q & 1) * 8;
                atomicMin(&red[r], enc(rmin[q]));
            }
            __syncthreads();
            #pragma unroll
            for (int mt = 0; mt < 2; mt++) {
                int r0 = mt * 16 + g;
                float t0 = dec(red[r0]) + th;
                float t1 = dec(red[r0 + 8]) + th;
                #pragma unroll
                for (int ntl = 0; ntl < 4; ntl++) {
                    int c0 = ntB + wn * 32 + ntl * 8 + 2 * tig;
                    float e0 = __ldg(&g_esq[c0]);
                    float e1 = __ldg(&g_esq[c0 + 1]);
                    float s0 = e0 - 2.0f * acc[mt][ntl][0];
                    float s1 = e1 - 2.0f * acc[mt][ntl][1];
                    float s2 = e0 - 2.0f * acc[mt][ntl][2];
                    float s3 = e1 - 2.0f * acc[mt][ntl][3];
                    if (s0 <= t0) append_cand(mBase + r0, c0);
                    if (s1 <= t0) append_cand(mBase + r0, c0 + 1);
                    if (s2 <= t1) append_cand(mBase + r0 + 8, c0);
                    if (s3 <= t1) append_cand(mBase + r0 + 8, c0 + 1);
                }
            }
        }
    }
}

// ---------------------------------------------------------------------------
// Pass 2: fp32 rescore, warp per row, whole warp per candidate, prefetched.
// ---------------------------------------------------------------------------
__global__ __launch_bounds__(256) void vq2_kernel(
    const float* __restrict__ x,
    const float* __restrict__ embed,
    float* __restrict__ out)
{
    const int wid  = threadIdx.x >> 5;
    const int lane = threadIdx.x & 31;
    const int R = blockIdx.x * 8 + wid;

    const float4* xr = (const float4*)(x + (size_t)R * D_DIM);
    float4 xa = xr[lane * 2], xb = xr[lane * 2 + 1];

    int cnt = g_cnt[R];
    float bd = 3.4e38f;
    int   bi = 0x7FFFFFFF;

    const bool uselist = (cnt <= CAND_MAX);
    const int  limit   = uselist ? cnt : N_TOT;
    const int* list    = g_cand + (size_t)R * CAND_MAX;

    int cd = uselist ? (limit > 0 ? list[0] : 0) : 0;
    const float4* er = (const float4*)(embed + (size_t)cd * D_DIM);
    float4 ea = er[lane * 2], eb = er[lane * 2 + 1];

    for (int ci = 0; ci < limit; ci++) {
        int curcd = cd;
        float4 ca = ea, cb = eb;
        if (ci + 1 < limit) {
            cd = uselist ? list[ci + 1] : (ci + 1);
            er = (const float4*)(embed + (size_t)cd * D_DIM);
            ea = er[lane * 2]; eb = er[lane * 2 + 1];
        }
        float d0 = xa.x * ca.x + xa.y * ca.y + xa.z * ca.z + xa.w * ca.w;
        float d1 = xb.x * cb.x + xb.y * cb.y + xb.z * cb.z + xb.w * cb.w;
        float dot = d0 + d1;
        #pragma unroll
        for (int o = 16; o; o >>= 1)
            dot += __shfl_xor_sync(0xFFFFFFFFu, dot, o);
        float s = g_esq[curcd] - 2.0f * dot;
        if (s < bd || (s == bd && curcd < bi)) { bd = s; bi = curcd; }
    }

    if (lane == 0) out[(size_t)M_TOT * D_DIM + R] = (float)bi;

    const float4* src = (const float4*)(embed + (size_t)bi * D_DIM);
    float4* dst = (float4*)(out + (size_t)R * D_DIM);
    #pragma unroll
    for (int t = lane; t < 64; t += 32) dst[t] = src[t];
}

// ---------------------------------------------------------------------------
extern "C" void kernel_launch(void* const* d_in, const int* in_sizes, int n_in,
                              void* d_out, int out_size)
{
    const float* x     = (const float*)d_in[0];
    const float* embed = (const float*)d_in[1];
    float*       out   = (float*)d_out;

    prep_embed<<<N_TOT / 8, 256>>>(embed);
    prep_x<<<M_TOT / 8, 256>>>(x);

    cudaFuncSetAttribute(vq1_kernel,
                         cudaFuncAttributeMaxDynamicSharedMemorySize, SM_BYTES);
    vq1_kernel<<<M_TOT / TM, NTHREADS, SM_BYTES>>>(x);

    vq2_kernel<<<M_TOT / 8, 256>>>(x, embed, out);
}